// round 1
// baseline (speedup 1.0000x reference)
#include <cuda_runtime.h>
#include <math.h>

// Problem dims (fixed by the reference)
#define B_    2
#define L_    2048
#define BL    4096          // B_*L_
#define NE    1024          // n_embd
#define DI    2048          // d_inner
#define DS    16            // d_state
#define DTR   64            // dt_rank
#define XP    96            // dt_rank + 2*d_state

// ---------------- scratch (static __device__ arrays; no allocation) -------
__device__ float g_Xn[BL * NE];        // layernorm output          16 MB
__device__ float g_XZ[BL * 2 * DI];    // in_proj output (u | res)  64 MB
__device__ float g_Uc[BL * DI];        // conv+silu output          32 MB
__device__ float g_XD[BL * XP];        // x_proj output             1.5 MB
__device__ float g_Dl[BL * DI];        // delta (post softplus)     32 MB
__device__ float g_Yg[BL * DI];        // scan output, gated        32 MB

// ---------------- LayerNorm: one block per token, 256 thr, float4 --------
__global__ void ln_kernel(const float* __restrict__ x,
                          const float* __restrict__ g,
                          const float* __restrict__ b,
                          float* __restrict__ out) {
    int row = blockIdx.x;
    int tid = threadIdx.x;                    // 0..255, NE/4 == 256
    const float4* xr = (const float4*)(x + (size_t)row * NE);
    float4 v = xr[tid];
    float s  = v.x + v.y + v.z + v.w;
    float s2 = v.x*v.x + v.y*v.y + v.z*v.z + v.w*v.w;

    __shared__ float red0[8], red1[8];
    __shared__ float mv[2];
    int wid = tid >> 5, lane = tid & 31;
    #pragma unroll
    for (int o = 16; o; o >>= 1) {
        s  += __shfl_xor_sync(0xffffffffu, s,  o);
        s2 += __shfl_xor_sync(0xffffffffu, s2, o);
    }
    if (lane == 0) { red0[wid] = s; red1[wid] = s2; }
    __syncthreads();
    if (tid == 0) {
        float a = 0.f, c = 0.f;
        #pragma unroll
        for (int i = 0; i < 8; i++) { a += red0[i]; c += red1[i]; }
        float mean = a * (1.0f / NE);
        float var  = c * (1.0f / NE) - mean * mean;
        mv[0] = mean;
        mv[1] = rsqrtf(var + 1e-5f);
    }
    __syncthreads();
    float mean = mv[0], inv = mv[1];
    float4 gv = ((const float4*)g)[tid];
    float4 bv = ((const float4*)b)[tid];
    float4 o4;
    o4.x = (v.x - mean) * inv * gv.x + bv.x;
    o4.y = (v.y - mean) * inv * gv.y + bv.y;
    o4.z = (v.z - mean) * inv * gv.z + bv.z;
    o4.w = (v.w - mean) * inv * gv.w + bv.w;
    ((float4*)(out + (size_t)row * NE))[tid] = o4;
}

// ---------------- Generic SGEMM: C[M,N] = A[M,K] * W[N,K]^T + epilogue ----
// BM=BN=128, BK=16, 256 threads, 8x8 microtile per thread.
// Assumes M % 128 == 0 and K % 16 == 0 (true for every call here).
// N is guarded (needed for x_proj where N = 96).
// EPI: 0 = none, 1 = softplus(acc + ext[n]), 2 = acc + ext[m*N + n]
template <int EPI>
__global__ void gemm_kernel(const float* __restrict__ A,
                            const float* __restrict__ W,
                            float* __restrict__ C,
                            int M, int N, int K, int lda,
                            const float* __restrict__ ext) {
    __shared__ float As[16][128];
    __shared__ float Bs[16][128];

    int tid = threadIdx.x;            // 256
    int tx = tid & 15, ty = tid >> 4; // 16 x 16
    int m0 = blockIdx.y * 128;
    int n0 = blockIdx.x * 128;

    float acc[8][8];
    #pragma unroll
    for (int i = 0; i < 8; i++)
        #pragma unroll
        for (int j = 0; j < 8; j++) acc[i][j] = 0.f;

    for (int k0 = 0; k0 < K; k0 += 16) {
        // load A tile (128 x 16) and W tile (128 x 16), store transposed
        #pragma unroll
        for (int t = 0; t < 2; t++) {
            int i   = tid + t * 256;       // float4 index 0..511
            int row = i >> 2;
            int kq  = (i & 3) << 2;
            // A
            float4 av = *(const float4*)(A + (size_t)(m0 + row) * lda + k0 + kq);
            As[kq + 0][row] = av.x;
            As[kq + 1][row] = av.y;
            As[kq + 2][row] = av.z;
            As[kq + 3][row] = av.w;
            // W (guard N)
            float4 wv = make_float4(0.f, 0.f, 0.f, 0.f);
            if (n0 + row < N)
                wv = *(const float4*)(W + (size_t)(n0 + row) * K + k0 + kq);
            Bs[kq + 0][row] = wv.x;
            Bs[kq + 1][row] = wv.y;
            Bs[kq + 2][row] = wv.z;
            Bs[kq + 3][row] = wv.w;
        }
        __syncthreads();

        #pragma unroll
        for (int k = 0; k < 16; k++) {
            float a[8], b[8];
            *(float4*)&a[0] = *(const float4*)&As[k][ty * 8 + 0];
            *(float4*)&a[4] = *(const float4*)&As[k][ty * 8 + 4];
            *(float4*)&b[0] = *(const float4*)&Bs[k][tx * 8 + 0];
            *(float4*)&b[4] = *(const float4*)&Bs[k][tx * 8 + 4];
            #pragma unroll
            for (int i = 0; i < 8; i++)
                #pragma unroll
                for (int j = 0; j < 8; j++)
                    acc[i][j] = fmaf(a[i], b[j], acc[i][j]);
        }
        __syncthreads();
    }

    // epilogue
    #pragma unroll
    for (int i = 0; i < 8; i++) {
        int m = m0 + ty * 8 + i;
        #pragma unroll
        for (int j = 0; j < 8; j++) {
            int n = n0 + tx * 8 + j;
            if (n < N) {
                float v = acc[i][j];
                if (EPI == 1) {
                    v = v + ext[n];
                    v = (v > 20.f) ? v : log1pf(__expf(v));   // softplus
                } else if (EPI == 2) {
                    v = v + ext[(size_t)m * N + n];           // residual
                }
                C[(size_t)m * N + n] = v;
            }
        }
    }
}

// ---------------- Causal depthwise conv (k=4) + bias + SiLU --------------
__global__ void conv_kernel(const float* __restrict__ xz,
                            const float* __restrict__ cw,
                            const float* __restrict__ cb,
                            float* __restrict__ uc) {
    int idx = blockIdx.x * blockDim.x + threadIdx.x;   // BL*DI
    if (idx >= BL * DI) return;
    int d = idx % DI;
    int t = idx / DI;           // b*L + l
    int l = t % L_;
    int base = t - l;           // b*L
    float acc = cb[d];
    #pragma unroll
    for (int k = 0; k < 4; k++) {
        int ls = l - 3 + k;
        if (ls >= 0)
            acc = fmaf(cw[d * 4 + k],
                       xz[(size_t)(base + ls) * (2 * DI) + d], acc);
    }
    float sig = 1.f / (1.f + __expf(-acc));
    uc[idx] = acc * sig;
}

// ---------------- Selective scan + skip + gate ---------------------------
// Half-warp per channel: 16 lanes = 16 states. 256 thr = 16 channels/block.
__global__ void scan_kernel(const float* __restrict__ xd,   // (BL, 96)
                            const float* __restrict__ dl,   // (BL, DI) delta
                            const float* __restrict__ uc,   // (BL, DI)
                            const float* __restrict__ xz,   // (BL, 2*DI) res half
                            const float* __restrict__ A_log,// (DI, DS)
                            const float* __restrict__ Dp,   // (DI)
                            float* __restrict__ yg) {
    int tid = threadIdx.x;
    int grp = tid >> 4;                 // channel within block
    int s   = tid & 15;                 // state index
    int c   = blockIdx.x * 16 + grp;    // global channel 0..4095
    int b   = c / DI;
    int d   = c % DI;

    float Av = -__expf(A_log[d * DS + s]);
    float Dd = Dp[d];
    float h  = 0.f;

    const size_t base_xd = (size_t)(b * L_) * XP;
    const size_t base_c  = (size_t)(b * L_) * DI + d;
    const size_t base_r  = (size_t)(b * L_) * (2 * DI) + DI + d;

    for (int l = 0; l < L_; l++) {
        size_t rb = base_xd + (size_t)l * XP;
        float Bt = xd[rb + DTR + s];
        float Ct = xd[rb + DTR + DS + s];
        size_t ci = base_c + (size_t)l * DI;
        float delta = dl[ci];
        float u     = uc[ci];
        float dA = __expf(delta * Av);
        h = fmaf(dA, h, delta * u * Bt);
        float p = h * Ct;
        p += __shfl_xor_sync(0xffffffffu, p, 8, 16);
        p += __shfl_xor_sync(0xffffffffu, p, 4, 16);
        p += __shfl_xor_sync(0xffffffffu, p, 2, 16);
        p += __shfl_xor_sync(0xffffffffu, p, 1, 16);
        if (s == 0) {
            float y = p + u * Dd;
            float r = xz[base_r + (size_t)l * (2 * DI)];
            float sil = r / (1.f + __expf(-r));
            yg[ci] = y * sil;
        }
    }
}

// ---------------- launch --------------------------------------------------
extern "C" void kernel_launch(void* const* d_in, const int* in_sizes, int n_in,
                              void* d_out, int out_size) {
    const float* x         = (const float*)d_in[0];
    const float* ln_g      = (const float*)d_in[1];
    const float* ln_b      = (const float*)d_in[2];
    const float* in_proj_w = (const float*)d_in[3];   // (2*DI, NE)
    const float* conv_w    = (const float*)d_in[4];   // (DI, 1, 4)
    const float* conv_b    = (const float*)d_in[5];   // (DI)
    const float* x_proj_w  = (const float*)d_in[6];   // (XP, DI)
    const float* dt_proj_w = (const float*)d_in[7];   // (DI, DTR)
    const float* dt_proj_b = (const float*)d_in[8];   // (DI)
    const float* A_log     = (const float*)d_in[9];   // (DI, DS)
    const float* Dp        = (const float*)d_in[10];  // (DI)
    const float* out_w     = (const float*)d_in[11];  // (NE, DI)
    float* out = (float*)d_out;

    float *Xn, *XZ, *Uc, *XD, *Dl, *Yg;
    cudaGetSymbolAddress((void**)&Xn, g_Xn);
    cudaGetSymbolAddress((void**)&XZ, g_XZ);
    cudaGetSymbolAddress((void**)&Uc, g_Uc);
    cudaGetSymbolAddress((void**)&XD, g_XD);
    cudaGetSymbolAddress((void**)&Dl, g_Dl);
    cudaGetSymbolAddress((void**)&Yg, g_Yg);

    // 1. LayerNorm
    ln_kernel<<<BL, 256>>>(x, ln_g, ln_b, Xn);

    // 2. in_proj: XZ[4096, 4096] = Xn[4096,1024] @ in_proj_w^T
    gemm_kernel<0><<<dim3(32, 32), 256>>>(Xn, in_proj_w, XZ,
                                          BL, 2 * DI, NE, NE, nullptr);

    // 3. depthwise conv + SiLU on u half -> Uc
    conv_kernel<<<(BL * DI + 255) / 256, 256>>>(XZ, conv_w, conv_b, Uc);

    // 4. x_proj: XD[4096, 96] = Uc @ x_proj_w^T
    gemm_kernel<0><<<dim3(1, 32), 256>>>(Uc, x_proj_w, XD,
                                         BL, XP, DI, DI, nullptr);

    // 5. dt_proj + softplus: Dl[4096, 2048] = softplus(XD[:, :64] @ dt_proj_w^T + b)
    gemm_kernel<1><<<dim3(16, 32), 256>>>(XD, dt_proj_w, Dl,
                                          BL, DI, DTR, XP, dt_proj_b);

    // 6. selective scan + skip + gate -> Yg
    scan_kernel<<<DI * B_ / 16, 256>>>(XD, Dl, Uc, XZ, A_log, Dp, Yg);

    // 7. out_proj + residual: out = Yg @ out_w^T + x
    gemm_kernel<2><<<dim3(8, 32), 256>>>(Yg, out_w, out,
                                         BL, NE, DI, DI, x);
}

// round 2
// speedup vs baseline: 1.4620x; 1.4620x over previous
#include <cuda_runtime.h>
#include <math.h>
#include <stdint.h>

// Problem dims (fixed by the reference)
#define B_    2
#define L_    2048
#define BL    4096          // B_*L_
#define NE    1024          // n_embd
#define DI    2048          // d_inner
#define DS    16            // d_state
#define DTR   64            // dt_rank
#define XP    96            // dt_rank + 2*d_state

// ---------------- scratch (static __device__ arrays; no allocation) -------
__device__ float g_Xn[BL * NE];        // layernorm output
__device__ float g_XZ[BL * 2 * DI];    // in_proj output (u | res)
__device__ float g_Uc[BL * DI];        // conv+silu output
__device__ float g_XD[BL * XP];        // x_proj output
__device__ float g_Dl[BL * DI];        // delta (post softplus)
__device__ float g_Yg[BL * DI];        // scan output, gated

// ---------------- LayerNorm ----------------------------------------------
__global__ void ln_kernel(const float* __restrict__ x,
                          const float* __restrict__ g,
                          const float* __restrict__ b,
                          float* __restrict__ out) {
    int row = blockIdx.x;
    int tid = threadIdx.x;                    // 0..255, NE/4 == 256
    const float4* xr = (const float4*)(x + (size_t)row * NE);
    float4 v = xr[tid];
    float s  = v.x + v.y + v.z + v.w;
    float s2 = v.x*v.x + v.y*v.y + v.z*v.z + v.w*v.w;

    __shared__ float red0[8], red1[8];
    __shared__ float mv[2];
    int wid = tid >> 5, lane = tid & 31;
    #pragma unroll
    for (int o = 16; o; o >>= 1) {
        s  += __shfl_xor_sync(0xffffffffu, s,  o);
        s2 += __shfl_xor_sync(0xffffffffu, s2, o);
    }
    if (lane == 0) { red0[wid] = s; red1[wid] = s2; }
    __syncthreads();
    if (tid == 0) {
        float a = 0.f, c = 0.f;
        #pragma unroll
        for (int i = 0; i < 8; i++) { a += red0[i]; c += red1[i]; }
        float mean = a * (1.0f / NE);
        float var  = c * (1.0f / NE) - mean * mean;
        mv[0] = mean;
        mv[1] = rsqrtf(var + 1e-5f);
    }
    __syncthreads();
    float mean = mv[0], inv = mv[1];
    float4 gv = ((const float4*)g)[tid];
    float4 bv = ((const float4*)b)[tid];
    float4 o4;
    o4.x = (v.x - mean) * inv * gv.x + bv.x;
    o4.y = (v.y - mean) * inv * gv.y + bv.y;
    o4.z = (v.z - mean) * inv * gv.z + bv.z;
    o4.w = (v.w - mean) * inv * gv.w + bv.w;
    ((float4*)(out + (size_t)row * NE))[tid] = o4;
}

// ---------------- TF32 tensor-core GEMM ----------------------------------
// C[M,N] = A[M,K] @ W[N,K]^T, row-major A (stride lda), row-major W (stride K).
// BM=128, BN=128, BK=32. 256 threads. Warp grid 2(m) x 4(n); each warp:
// 64x32 via 4x4 tiles of mma.sync.m16n8k8.tf32.
// Requires M%128==0, K%32==0 (true for all calls). N guarded.
// EPI: 0 none, 1 softplus(acc+ext[n]), 2 acc+ext[m*N+n]
#define SPAD 36   // smem row stride in floats (conflict-free: bank=(4r+c)%32)

__device__ __forceinline__ uint32_t f2tf32(float f) {
    uint32_t r;
    asm("cvt.rna.tf32.f32 %0, %1;" : "=r"(r) : "f"(f));
    return r;
}

template <int EPI>
__global__ void __launch_bounds__(256)
tgemm(const float* __restrict__ A, const float* __restrict__ W,
      float* __restrict__ C, int M, int N, int K, int lda,
      const float* __restrict__ ext) {
    __shared__ uint32_t As[128 * SPAD];
    __shared__ uint32_t Bs[128 * SPAD];

    const int tid  = threadIdx.x;
    const int lane = tid & 31;
    const int wid  = tid >> 5;
    const int warp_m = wid >> 2;       // 0..1
    const int warp_n = wid & 3;        // 0..3
    const int wm0 = warp_m * 64;
    const int wn0 = warp_n * 32;
    const int grp = lane >> 2;         // 0..7
    const int thr = lane & 3;          // 0..3

    const int m0 = blockIdx.y * 128;
    const int n0 = blockIdx.x * 128;

    float acc[4][4][4];
    #pragma unroll
    for (int i = 0; i < 4; i++)
        #pragma unroll
        for (int j = 0; j < 4; j++)
            #pragma unroll
            for (int q = 0; q < 4; q++) acc[i][j][q] = 0.f;

    float4 a_stg[4], b_stg[4];

    // ---- stage 0 loads
    auto load_stage = [&](int k0) {
        #pragma unroll
        for (int t = 0; t < 4; t++) {
            int f   = tid + t * 256;       // 0..1023
            int row = f >> 3;
            int kq  = (f & 7) << 2;
            a_stg[t] = *(const float4*)(A + (size_t)(m0 + row) * lda + k0 + kq);
            if (n0 + row < N)
                b_stg[t] = *(const float4*)(W + (size_t)(n0 + row) * K + k0 + kq);
            else
                b_stg[t] = make_float4(0.f, 0.f, 0.f, 0.f);
        }
    };
    auto store_stage = [&]() {
        #pragma unroll
        for (int t = 0; t < 4; t++) {
            int f   = tid + t * 256;
            int row = f >> 3;
            int kq  = (f & 7) << 2;
            uint32_t* ap = &As[row * SPAD + kq];
            ap[0] = f2tf32(a_stg[t].x); ap[1] = f2tf32(a_stg[t].y);
            ap[2] = f2tf32(a_stg[t].z); ap[3] = f2tf32(a_stg[t].w);
            uint32_t* bp = &Bs[row * SPAD + kq];
            bp[0] = f2tf32(b_stg[t].x); bp[1] = f2tf32(b_stg[t].y);
            bp[2] = f2tf32(b_stg[t].z); bp[3] = f2tf32(b_stg[t].w);
        }
    };

    load_stage(0);
    store_stage();
    __syncthreads();

    for (int k0 = 0; k0 < K; k0 += 32) {
        bool last = (k0 + 32 >= K);
        if (!last) load_stage(k0 + 32);

        #pragma unroll
        for (int ks = 0; ks < 4; ks++) {
            uint32_t af[4][4], bf[4][2];
            #pragma unroll
            for (int ti = 0; ti < 4; ti++) {
                int r = wm0 + ti * 16 + grp;
                const uint32_t* base = &As[r * SPAD + ks * 8 + thr];
                af[ti][0] = base[0];
                af[ti][1] = base[8 * SPAD];
                af[ti][2] = base[4];
                af[ti][3] = base[8 * SPAD + 4];
            }
            #pragma unroll
            for (int tj = 0; tj < 4; tj++) {
                int n = wn0 + tj * 8 + grp;
                const uint32_t* base = &Bs[n * SPAD + ks * 8 + thr];
                bf[tj][0] = base[0];
                bf[tj][1] = base[4];
            }
            #pragma unroll
            for (int ti = 0; ti < 4; ti++)
                #pragma unroll
                for (int tj = 0; tj < 4; tj++) {
                    asm volatile(
                        "mma.sync.aligned.m16n8k8.row.col.f32.tf32.tf32.f32 "
                        "{%0,%1,%2,%3}, {%4,%5,%6,%7}, {%8,%9}, {%0,%1,%2,%3};"
                        : "+f"(acc[ti][tj][0]), "+f"(acc[ti][tj][1]),
                          "+f"(acc[ti][tj][2]), "+f"(acc[ti][tj][3])
                        : "r"(af[ti][0]), "r"(af[ti][1]),
                          "r"(af[ti][2]), "r"(af[ti][3]),
                          "r"(bf[tj][0]), "r"(bf[tj][1]));
                }
        }
        __syncthreads();
        if (!last) {
            store_stage();
            __syncthreads();
        }
    }

    // ---- epilogue
    #pragma unroll
    for (int ti = 0; ti < 4; ti++) {
        #pragma unroll
        for (int tj = 0; tj < 4; tj++) {
            int r0 = m0 + wm0 + ti * 16 + grp;
            int c  = n0 + wn0 + tj * 8 + thr * 2;
            if (c < N) {
                #pragma unroll
                for (int half = 0; half < 2; half++) {
                    int r = r0 + half * 8;
                    float v0 = acc[ti][tj][half * 2 + 0];
                    float v1 = acc[ti][tj][half * 2 + 1];
                    if (EPI == 1) {
                        v0 += ext[c];     v1 += ext[c + 1];
                        v0 = (v0 > 20.f) ? v0 : log1pf(__expf(v0));
                        v1 = (v1 > 20.f) ? v1 : log1pf(__expf(v1));
                    } else if (EPI == 2) {
                        v0 += ext[(size_t)r * N + c];
                        v1 += ext[(size_t)r * N + c + 1];
                    }
                    *(float2*)(C + (size_t)r * N + c) = make_float2(v0, v1);
                }
            }
        }
    }
}

// ---------------- Causal depthwise conv (k=4) + bias + SiLU --------------
__global__ void conv_kernel(const float* __restrict__ xz,
                            const float* __restrict__ cw,
                            const float* __restrict__ cb,
                            float* __restrict__ uc) {
    int idx = blockIdx.x * blockDim.x + threadIdx.x;   // BL*DI
    if (idx >= BL * DI) return;
    int d = idx % DI;
    int t = idx / DI;           // b*L + l
    int l = t % L_;
    int base = t - l;           // b*L
    float acc = cb[d];
    #pragma unroll
    for (int k = 0; k < 4; k++) {
        int ls = l - 3 + k;
        if (ls >= 0)
            acc = fmaf(cw[d * 4 + k],
                       xz[(size_t)(base + ls) * (2 * DI) + d], acc);
    }
    float sig = 1.f / (1.f + __expf(-acc));
    uc[idx] = acc * sig;
}

// ---------------- Selective scan + skip + gate ---------------------------
__global__ void scan_kernel(const float* __restrict__ xd,   // (BL, 96)
                            const float* __restrict__ dl,   // (BL, DI) delta
                            const float* __restrict__ uc,   // (BL, DI)
                            const float* __restrict__ xz,   // (BL, 2*DI) res half
                            const float* __restrict__ A_log,// (DI, DS)
                            const float* __restrict__ Dp,   // (DI)
                            float* __restrict__ yg) {
    int tid = threadIdx.x;
    int grp = tid >> 4;                 // channel within block
    int s   = tid & 15;                 // state index
    int c   = blockIdx.x * 16 + grp;    // global channel 0..4095
    int b   = c / DI;
    int d   = c % DI;

    float Av = -__expf(A_log[d * DS + s]);
    float Dd = Dp[d];
    float h  = 0.f;

    const size_t base_xd = (size_t)(b * L_) * XP;
    const size_t base_c  = (size_t)(b * L_) * DI + d;
    const size_t base_r  = (size_t)(b * L_) * (2 * DI) + DI + d;

    for (int l = 0; l < L_; l++) {
        size_t rb = base_xd + (size_t)l * XP;
        float Bt = xd[rb + DTR + s];
        float Ct = xd[rb + DTR + DS + s];
        size_t ci = base_c + (size_t)l * DI;
        float delta = dl[ci];
        float u     = uc[ci];
        float dA = __expf(delta * Av);
        h = fmaf(dA, h, delta * u * Bt);
        float p = h * Ct;
        p += __shfl_xor_sync(0xffffffffu, p, 8, 16);
        p += __shfl_xor_sync(0xffffffffu, p, 4, 16);
        p += __shfl_xor_sync(0xffffffffu, p, 2, 16);
        p += __shfl_xor_sync(0xffffffffu, p, 1, 16);
        if (s == 0) {
            float y = p + u * Dd;
            float r = xz[base_r + (size_t)l * (2 * DI)];
            float sil = r / (1.f + __expf(-r));
            yg[ci] = y * sil;
        }
    }
}

// ---------------- launch --------------------------------------------------
extern "C" void kernel_launch(void* const* d_in, const int* in_sizes, int n_in,
                              void* d_out, int out_size) {
    const float* x         = (const float*)d_in[0];
    const float* ln_g      = (const float*)d_in[1];
    const float* ln_b      = (const float*)d_in[2];
    const float* in_proj_w = (const float*)d_in[3];   // (2*DI, NE)
    const float* conv_w    = (const float*)d_in[4];   // (DI, 1, 4)
    const float* conv_b    = (const float*)d_in[5];   // (DI)
    const float* x_proj_w  = (const float*)d_in[6];   // (XP, DI)
    const float* dt_proj_w = (const float*)d_in[7];   // (DI, DTR)
    const float* dt_proj_b = (const float*)d_in[8];   // (DI)
    const float* A_log     = (const float*)d_in[9];   // (DI, DS)
    const float* Dp        = (const float*)d_in[10];  // (DI)
    const float* out_w     = (const float*)d_in[11];  // (NE, DI)
    float* out = (float*)d_out;

    float *Xn, *XZ, *Uc, *XD, *Dl, *Yg;
    cudaGetSymbolAddress((void**)&Xn, g_Xn);
    cudaGetSymbolAddress((void**)&XZ, g_XZ);
    cudaGetSymbolAddress((void**)&Uc, g_Uc);
    cudaGetSymbolAddress((void**)&XD, g_XD);
    cudaGetSymbolAddress((void**)&Dl, g_Dl);
    cudaGetSymbolAddress((void**)&Yg, g_Yg);

    // 1. LayerNorm
    ln_kernel<<<BL, 256>>>(x, ln_g, ln_b, Xn);

    // 2. in_proj: XZ[4096, 4096] = Xn[4096,1024] @ in_proj_w^T
    tgemm<0><<<dim3(32, 32), 256>>>(Xn, in_proj_w, XZ,
                                    BL, 2 * DI, NE, NE, nullptr);

    // 3. depthwise conv + SiLU on u half -> Uc
    conv_kernel<<<(BL * DI + 255) / 256, 256>>>(XZ, conv_w, conv_b, Uc);

    // 4. x_proj: XD[4096, 96] = Uc @ x_proj_w^T
    tgemm<0><<<dim3(1, 32), 256>>>(Uc, x_proj_w, XD,
                                   BL, XP, DI, DI, nullptr);

    // 5. dt_proj + softplus: Dl[4096, 2048] = softplus(XD[:, :64] @ dt_proj_w^T + b)
    tgemm<1><<<dim3(16, 32), 256>>>(XD, dt_proj_w, Dl,
                                    BL, DI, DTR, XP, dt_proj_b);

    // 6. selective scan + skip + gate -> Yg
    scan_kernel<<<DI * B_ / 16, 256>>>(XD, Dl, Uc, XZ, A_log, Dp, Yg);

    // 7. out_proj + residual: out = Yg @ out_w^T + x
    tgemm<2><<<dim3(8, 32), 256>>>(Yg, out_w, out,
                                   BL, NE, DI, DI, x);
}

// round 3
// speedup vs baseline: 3.1387x; 2.1468x over previous
#include <cuda_runtime.h>
#include <math.h>
#include <stdint.h>

// Problem dims (fixed by the reference)
#define B_    2
#define L_    2048
#define BL    4096          // B_*L_
#define NE    1024          // n_embd
#define DI    2048          // d_inner
#define DS    16            // d_state
#define DTR   64            // dt_rank
#define XP    96            // dt_rank + 2*d_state
#define NCH   16            // scan chunks
#define CL    (L_ / NCH)    // 128 steps per chunk

// ---------------- scratch (static __device__ arrays; no allocation) -------
__device__ float g_Xn[BL * NE];        // layernorm output
__device__ float g_XZ[BL * 2 * DI];    // in_proj output (u | res)
__device__ float g_Uc[BL * DI];        // conv+silu output
__device__ float g_XD[BL * XP];        // x_proj output
__device__ float g_Dl[BL * DI];        // delta (post softplus)
__device__ float g_Yg[BL * DI];        // scan output, gated
__device__ float g_hF[B_ * DI * NCH * DS];   // chunk-final states   (4MB)
__device__ float g_Pf[B_ * DI * NCH * DS];   // chunk dA products    (4MB)
__device__ float g_hI[B_ * DI * NCH * DS];   // chunk initial states (4MB)

// ---------------- LayerNorm ----------------------------------------------
__global__ void ln_kernel(const float* __restrict__ x,
                          const float* __restrict__ g,
                          const float* __restrict__ b,
                          float* __restrict__ out) {
    int row = blockIdx.x;
    int tid = threadIdx.x;                    // 0..255, NE/4 == 256
    const float4* xr = (const float4*)(x + (size_t)row * NE);
    float4 v = xr[tid];
    float s  = v.x + v.y + v.z + v.w;
    float s2 = v.x*v.x + v.y*v.y + v.z*v.z + v.w*v.w;

    __shared__ float red0[8], red1[8];
    __shared__ float mv[2];
    int wid = tid >> 5, lane = tid & 31;
    #pragma unroll
    for (int o = 16; o; o >>= 1) {
        s  += __shfl_xor_sync(0xffffffffu, s,  o);
        s2 += __shfl_xor_sync(0xffffffffu, s2, o);
    }
    if (lane == 0) { red0[wid] = s; red1[wid] = s2; }
    __syncthreads();
    if (tid == 0) {
        float a = 0.f, c = 0.f;
        #pragma unroll
        for (int i = 0; i < 8; i++) { a += red0[i]; c += red1[i]; }
        float mean = a * (1.0f / NE);
        float var  = c * (1.0f / NE) - mean * mean;
        mv[0] = mean;
        mv[1] = rsqrtf(var + 1e-5f);
    }
    __syncthreads();
    float mean = mv[0], inv = mv[1];
    float4 gv = ((const float4*)g)[tid];
    float4 bv = ((const float4*)b)[tid];
    float4 o4;
    o4.x = (v.x - mean) * inv * gv.x + bv.x;
    o4.y = (v.y - mean) * inv * gv.y + bv.y;
    o4.z = (v.z - mean) * inv * gv.z + bv.z;
    o4.w = (v.w - mean) * inv * gv.w + bv.w;
    ((float4*)(out + (size_t)row * NE))[tid] = o4;
}

// ---------------- TF32 tensor-core GEMM with cp.async pipeline -----------
// C[M,N] = A[M,K] @ W[N,K]^T. BM=BN=128, BK=32, 256 thr, 2-stage cp.async.
// EPI: 0 none, 1 softplus(acc+ext[n]), 2 acc+ext[m*N+n]
#define SPAD 36   // smem row stride (conflict-free: bank 4g+t bijective)
#define STG_U32 (128 * SPAD)          // uint32 per tile buffer

__device__ __forceinline__ void cpa16(uint32_t dst, const void* src, bool p) {
    int sz = p ? 16 : 0;
    asm volatile("cp.async.cg.shared.global [%0], [%1], 16, %2;\n"
                 :: "r"(dst), "l"(src), "r"(sz));
}
__device__ __forceinline__ void cpa_commit() {
    asm volatile("cp.async.commit_group;\n");
}
template <int N>
__device__ __forceinline__ void cpa_wait() {
    asm volatile("cp.async.wait_group %0;\n" :: "n"(N));
}

template <int EPI>
__global__ void __launch_bounds__(256, 2)
tgemm(const float* __restrict__ A, const float* __restrict__ W,
      float* __restrict__ C, int M, int N, int K, int lda,
      const float* __restrict__ ext) {
    extern __shared__ uint32_t smem[];
    // layout: As[stage] at stage*STG_U32, Bs[stage] at 2*STG_U32 + stage*STG_U32
    const int tid  = threadIdx.x;
    const int lane = tid & 31;
    const int wid  = tid >> 5;
    const int wm0 = (wid >> 2) * 64;
    const int wn0 = (wid & 3) * 32;
    const int grp = lane >> 2;         // 0..7
    const int thr = lane & 3;          // 0..3

    const int m0 = blockIdx.y * 128;
    const int n0 = blockIdx.x * 128;

    uint32_t smem_base;
    asm("{ .reg .u64 t; cvta.to.shared.u64 t, %1; cvt.u32.u64 %0, t; }"
        : "=r"(smem_base) : "l"(smem));

    float acc[4][4][4];
    #pragma unroll
    for (int i = 0; i < 4; i++)
        #pragma unroll
        for (int j = 0; j < 4; j++)
            #pragma unroll
            for (int q = 0; q < 4; q++) acc[i][j][q] = 0.f;

    const int row  = tid >> 3;           // 0..31 base row (stride 32 over t)
    const int kq   = (tid & 7) << 2;     // 0,4,..,28

    auto issue = [&](int tile, int stage) {
        int k0 = tile * 32;
        #pragma unroll
        for (int t = 0; t < 4; t++) {
            int r = row + t * 32;
            uint32_t da = smem_base + (stage * STG_U32 + r * SPAD + kq) * 4;
            cpa16(da, A + (size_t)(m0 + r) * lda + k0 + kq, true);
            uint32_t db = smem_base + ((2 + stage) * STG_U32 + r * SPAD + kq) * 4;
            cpa16(db, W + (size_t)(n0 + r) * K + k0 + kq, (n0 + r) < N);
        }
        cpa_commit();
    };

    const int T = K >> 5;
    issue(0, 0);
    if (T > 1) issue(1, 1);

    for (int t = 0; t < T; t++) {
        if (t < T - 1) cpa_wait<1>(); else cpa_wait<0>();
        __syncthreads();

        const uint32_t* As = smem + (t & 1) * STG_U32;
        const uint32_t* Bs = smem + (2 + (t & 1)) * STG_U32;

        #pragma unroll
        for (int ks = 0; ks < 4; ks++) {
            uint32_t af[4][4], bf[4][2];
            #pragma unroll
            for (int ti = 0; ti < 4; ti++) {
                const uint32_t* base = &As[(wm0 + ti * 16 + grp) * SPAD + ks * 8 + thr];
                af[ti][0] = base[0];
                af[ti][1] = base[8 * SPAD];
                af[ti][2] = base[4];
                af[ti][3] = base[8 * SPAD + 4];
            }
            #pragma unroll
            for (int tj = 0; tj < 4; tj++) {
                const uint32_t* base = &Bs[(wn0 + tj * 8 + grp) * SPAD + ks * 8 + thr];
                bf[tj][0] = base[0];
                bf[tj][1] = base[4];
            }
            #pragma unroll
            for (int ti = 0; ti < 4; ti++)
                #pragma unroll
                for (int tj = 0; tj < 4; tj++) {
                    asm volatile(
                        "mma.sync.aligned.m16n8k8.row.col.f32.tf32.tf32.f32 "
                        "{%0,%1,%2,%3}, {%4,%5,%6,%7}, {%8,%9}, {%0,%1,%2,%3};"
                        : "+f"(acc[ti][tj][0]), "+f"(acc[ti][tj][1]),
                          "+f"(acc[ti][tj][2]), "+f"(acc[ti][tj][3])
                        : "r"(af[ti][0]), "r"(af[ti][1]),
                          "r"(af[ti][2]), "r"(af[ti][3]),
                          "r"(bf[tj][0]), "r"(bf[tj][1]));
                }
        }
        __syncthreads();
        if (t + 2 < T) issue(t + 2, t & 1);
    }

    // ---- epilogue
    #pragma unroll
    for (int ti = 0; ti < 4; ti++) {
        #pragma unroll
        for (int tj = 0; tj < 4; tj++) {
            int r0 = m0 + wm0 + ti * 16 + grp;
            int c  = n0 + wn0 + tj * 8 + thr * 2;
            if (c < N) {
                #pragma unroll
                for (int half = 0; half < 2; half++) {
                    int r = r0 + half * 8;
                    float v0 = acc[ti][tj][half * 2 + 0];
                    float v1 = acc[ti][tj][half * 2 + 1];
                    if (EPI == 1) {
                        v0 += ext[c];     v1 += ext[c + 1];
                        v0 = (v0 > 20.f) ? v0 : log1pf(__expf(v0));
                        v1 = (v1 > 20.f) ? v1 : log1pf(__expf(v1));
                    } else if (EPI == 2) {
                        v0 += ext[(size_t)r * N + c];
                        v1 += ext[(size_t)r * N + c + 1];
                    }
                    *(float2*)(C + (size_t)r * N + c) = make_float2(v0, v1);
                }
            }
        }
    }
}

// ---------------- Causal depthwise conv (k=4) + bias + SiLU --------------
__global__ void conv_kernel(const float* __restrict__ xz,
                            const float* __restrict__ cw,
                            const float* __restrict__ cb,
                            float* __restrict__ uc) {
    int idx = blockIdx.x * blockDim.x + threadIdx.x;   // BL*DI
    if (idx >= BL * DI) return;
    int d = idx % DI;
    int t = idx / DI;           // b*L + l
    int l = t % L_;
    int base = t - l;           // b*L
    float acc = cb[d];
    #pragma unroll
    for (int k = 0; k < 4; k++) {
        int ls = l - 3 + k;
        if (ls >= 0)
            acc = fmaf(cw[d * 4 + k],
                       xz[(size_t)(base + ls) * (2 * DI) + d], acc);
    }
    float sig = 1.f / (1.f + __expf(-acc));
    uc[idx] = acc * sig;
}

// ---------------- Chunked selective scan ---------------------------------
// Block: 256 thr = 16 groups of 16 lanes; 16 consecutive channels d,
// fixed (b, chunk). grid = (DI/16) * B_ * NCH = 4096 blocks.
// Phase A: local scan from h=0; store final h and prod(dA).
__global__ void __launch_bounds__(256)
scanA(const float* __restrict__ xd, const float* __restrict__ dl,
      const float* __restrict__ uc, const float* __restrict__ A_log,
      float* __restrict__ hF, float* __restrict__ Pf) {
    int tid = threadIdx.x;
    int grp = tid >> 4, s = tid & 15;
    int blk = blockIdx.x;
    int dgrp = blk & 127;               // DI/16 = 128
    int rest = blk >> 7;
    int chunk = rest & (NCH - 1);
    int b = rest >> 4;
    int d = dgrp * 16 + grp;

    float Av = -__expf(A_log[d * DS + s]);
    float h = 0.f, P = 1.f;
    int l0 = chunk * CL;
    const float* dlp = dl + (size_t)(b * L_ + l0) * DI + d;
    const float* ucp = uc + (size_t)(b * L_ + l0) * DI + d;
    const float* xdp = xd + (size_t)(b * L_ + l0) * XP + DTR + s;

    for (int i = 0; i < CL; i++) {
        float delta = dlp[(size_t)i * DI];
        float u     = ucp[(size_t)i * DI];
        float Bt    = xdp[(size_t)i * XP];
        float dA = __expf(delta * Av);
        h = fmaf(dA, h, delta * u * Bt);
        P *= dA;
    }
    size_t o = (((size_t)(b * DI + d)) * NCH + chunk) * DS + s;
    hF[o] = h;
    Pf[o] = P;
}

// Phase B: carry scan across chunks. Thread per (b,d,s) = 65536.
__global__ void scanB(const float* __restrict__ hF,
                      const float* __restrict__ Pf,
                      float* __restrict__ hI) {
    int idx = blockIdx.x * blockDim.x + threadIdx.x;
    if (idx >= B_ * DI * DS) return;
    size_t base = (size_t)(idx >> 4) * (NCH * DS) + (idx & 15);
    float h = 0.f;
    #pragma unroll
    for (int c = 0; c < NCH; c++) {
        size_t o = base + (size_t)c * DS;
        hI[o] = h;
        h = fmaf(Pf[o], h, hF[o]);
    }
}

// Phase C: replay chunk with correct h_in, produce gated y.
__global__ void __launch_bounds__(256)
scanC(const float* __restrict__ xd, const float* __restrict__ dl,
      const float* __restrict__ uc, const float* __restrict__ xz,
      const float* __restrict__ A_log, const float* __restrict__ Dp,
      const float* __restrict__ hI, float* __restrict__ yg) {
    int tid = threadIdx.x;
    int grp = tid >> 4, s = tid & 15;
    int blk = blockIdx.x;
    int dgrp = blk & 127;
    int rest = blk >> 7;
    int chunk = rest & (NCH - 1);
    int b = rest >> 4;
    int d = dgrp * 16 + grp;

    float Av = -__expf(A_log[d * DS + s]);
    float Dd = Dp[d];
    size_t o = (((size_t)(b * DI + d)) * NCH + chunk) * DS + s;
    float h = hI[o];

    int l0 = chunk * CL;
    const float* dlp = dl + (size_t)(b * L_ + l0) * DI + d;
    const float* ucp = uc + (size_t)(b * L_ + l0) * DI + d;
    const float* xdp = xd + (size_t)(b * L_ + l0) * XP + DTR;
    const float* xzp = xz + (size_t)(b * L_ + l0) * (2 * DI) + DI + d;
    float* ygp = yg + (size_t)(b * L_ + l0) * DI + d;

    for (int i = 0; i < CL; i++) {
        float delta = dlp[(size_t)i * DI];
        float u     = ucp[(size_t)i * DI];
        float Bt    = xdp[(size_t)i * XP + s];
        float Ct    = xdp[(size_t)i * XP + DS + s];
        float dA = __expf(delta * Av);
        h = fmaf(dA, h, delta * u * Bt);
        float p = h * Ct;
        p += __shfl_xor_sync(0xffffffffu, p, 8, 16);
        p += __shfl_xor_sync(0xffffffffu, p, 4, 16);
        p += __shfl_xor_sync(0xffffffffu, p, 2, 16);
        p += __shfl_xor_sync(0xffffffffu, p, 1, 16);
        if (s == 0) {
            float y = p + u * Dd;
            float r = xzp[(size_t)i * (2 * DI)];
            float sil = r / (1.f + __expf(-r));
            ygp[(size_t)i * DI] = y * sil;
        }
    }
}

// ---------------- launch --------------------------------------------------
#define GSMEM (4 * STG_U32 * 4)   // 4 buffers (A0,A1,B0,B1) in bytes

extern "C" void kernel_launch(void* const* d_in, const int* in_sizes, int n_in,
                              void* d_out, int out_size) {
    const float* x         = (const float*)d_in[0];
    const float* ln_g      = (const float*)d_in[1];
    const float* ln_b      = (const float*)d_in[2];
    const float* in_proj_w = (const float*)d_in[3];   // (2*DI, NE)
    const float* conv_w    = (const float*)d_in[4];   // (DI, 1, 4)
    const float* conv_b    = (const float*)d_in[5];   // (DI)
    const float* x_proj_w  = (const float*)d_in[6];   // (XP, DI)
    const float* dt_proj_w = (const float*)d_in[7];   // (DI, DTR)
    const float* dt_proj_b = (const float*)d_in[8];   // (DI)
    const float* A_log     = (const float*)d_in[9];   // (DI, DS)
    const float* Dp        = (const float*)d_in[10];  // (DI)
    const float* out_w     = (const float*)d_in[11];  // (NE, DI)
    float* out = (float*)d_out;

    float *Xn, *XZ, *Uc, *XD, *Dl, *Yg, *hF, *Pf, *hI;
    cudaGetSymbolAddress((void**)&Xn, g_Xn);
    cudaGetSymbolAddress((void**)&XZ, g_XZ);
    cudaGetSymbolAddress((void**)&Uc, g_Uc);
    cudaGetSymbolAddress((void**)&XD, g_XD);
    cudaGetSymbolAddress((void**)&Dl, g_Dl);
    cudaGetSymbolAddress((void**)&Yg, g_Yg);
    cudaGetSymbolAddress((void**)&hF, g_hF);
    cudaGetSymbolAddress((void**)&Pf, g_Pf);
    cudaGetSymbolAddress((void**)&hI, g_hI);

    static bool attr_set = false;
    if (!attr_set) {
        cudaFuncSetAttribute(tgemm<0>, cudaFuncAttributeMaxDynamicSharedMemorySize, GSMEM);
        cudaFuncSetAttribute(tgemm<1>, cudaFuncAttributeMaxDynamicSharedMemorySize, GSMEM);
        cudaFuncSetAttribute(tgemm<2>, cudaFuncAttributeMaxDynamicSharedMemorySize, GSMEM);
        attr_set = true;
    }

    // 1. LayerNorm
    ln_kernel<<<BL, 256>>>(x, ln_g, ln_b, Xn);

    // 2. in_proj: XZ[4096, 4096] = Xn[4096,1024] @ in_proj_w^T
    tgemm<0><<<dim3(32, 32), 256, GSMEM>>>(Xn, in_proj_w, XZ,
                                           BL, 2 * DI, NE, NE, nullptr);

    // 3. depthwise conv + SiLU on u half -> Uc
    conv_kernel<<<(BL * DI + 255) / 256, 256>>>(XZ, conv_w, conv_b, Uc);

    // 4. x_proj: XD[4096, 96] = Uc @ x_proj_w^T
    tgemm<0><<<dim3(1, 32), 256, GSMEM>>>(Uc, x_proj_w, XD,
                                          BL, XP, DI, DI, nullptr);

    // 5. dt_proj + softplus
    tgemm<1><<<dim3(16, 32), 256, GSMEM>>>(XD, dt_proj_w, Dl,
                                           BL, DI, DTR, XP, dt_proj_b);

    // 6. chunked selective scan
    scanA<<<(DI / 16) * B_ * NCH, 256>>>(XD, Dl, Uc, A_log, hF, Pf);
    scanB<<<(B_ * DI * DS + 255) / 256, 256>>>(hF, Pf, hI);
    scanC<<<(DI / 16) * B_ * NCH, 256>>>(XD, Dl, Uc, XZ, A_log, Dp, hI, Yg);

    // 7. out_proj + residual: out = Yg @ out_w^T + x
    tgemm<2><<<dim3(8, 32), 256, GSMEM>>>(Yg, out_w, out,
                                          BL, NE, DI, DI, x);
}

// round 4
// speedup vs baseline: 3.2849x; 1.0466x over previous
#include <cuda_runtime.h>
#include <math.h>
#include <stdint.h>

// Problem dims (fixed by the reference)
#define B_    2
#define L_    2048
#define BL    4096          // B_*L_
#define NE    1024          // n_embd
#define DI    2048          // d_inner
#define DS    16            // d_state
#define DTR   64            // dt_rank
#define XP    96            // dt_rank + 2*d_state
#define NCH   64            // scan chunks
#define CL    (L_ / NCH)    // 32 steps per chunk

// ---------------- scratch (static __device__ arrays; no allocation) -------
__device__ float g_Xn[BL * NE];        // layernorm output
__device__ float g_XZ[BL * 2 * DI];    // in_proj output (u | res)
__device__ float g_Uc[BL * DI];        // conv+silu output
__device__ float g_XD[BL * XP];        // x_proj output
__device__ float g_Dl[BL * DI];        // delta (post softplus)
__device__ float g_Yg[BL * DI];        // scan output, gated
__device__ float g_hF[B_ * DI * NCH * DS];   // chunk-final states
__device__ float g_Pf[B_ * DI * NCH * DS];   // chunk dA products
__device__ float g_hI[B_ * DI * NCH * DS];   // chunk initial states

// ---------------- LayerNorm ----------------------------------------------
__global__ void ln_kernel(const float* __restrict__ x,
                          const float* __restrict__ g,
                          const float* __restrict__ b,
                          float* __restrict__ out) {
    int row = blockIdx.x;
    int tid = threadIdx.x;                    // 0..255, NE/4 == 256
    const float4* xr = (const float4*)(x + (size_t)row * NE);
    float4 v = xr[tid];
    float s  = v.x + v.y + v.z + v.w;
    float s2 = v.x*v.x + v.y*v.y + v.z*v.z + v.w*v.w;

    __shared__ float red0[8], red1[8];
    __shared__ float mv[2];
    int wid = tid >> 5, lane = tid & 31;
    #pragma unroll
    for (int o = 16; o; o >>= 1) {
        s  += __shfl_xor_sync(0xffffffffu, s,  o);
        s2 += __shfl_xor_sync(0xffffffffu, s2, o);
    }
    if (lane == 0) { red0[wid] = s; red1[wid] = s2; }
    __syncthreads();
    if (tid == 0) {
        float a = 0.f, c = 0.f;
        #pragma unroll
        for (int i = 0; i < 8; i++) { a += red0[i]; c += red1[i]; }
        float mean = a * (1.0f / NE);
        float var  = c * (1.0f / NE) - mean * mean;
        mv[0] = mean;
        mv[1] = rsqrtf(var + 1e-5f);
    }
    __syncthreads();
    float mean = mv[0], inv = mv[1];
    float4 gv = ((const float4*)g)[tid];
    float4 bv = ((const float4*)b)[tid];
    float4 o4;
    o4.x = (v.x - mean) * inv * gv.x + bv.x;
    o4.y = (v.y - mean) * inv * gv.y + bv.y;
    o4.z = (v.z - mean) * inv * gv.z + bv.z;
    o4.w = (v.w - mean) * inv * gv.w + bv.w;
    ((float4*)(out + (size_t)row * NE))[tid] = o4;
}

// ---------------- TF32 tensor-core GEMM, 3-stage cp.async ----------------
// C[M,N] = A[M,K] @ W[N,K]^T. BM=BN=128, BK=32, 256 thr.
// EPI: 0 none, 1 softplus(acc+ext[n]), 2 acc+ext[m*N+n]
#define SPAD 36                    // smem row stride (conflict-free)
#define STG_U32 (128 * SPAD)       // u32 per tile buffer
#define NSTG 3

__device__ __forceinline__ void cpa16(uint32_t dst, const void* src, bool p) {
    int sz = p ? 16 : 0;
    asm volatile("cp.async.cg.shared.global [%0], [%1], 16, %2;\n"
                 :: "r"(dst), "l"(src), "r"(sz));
}
__device__ __forceinline__ void cpa_commit() {
    asm volatile("cp.async.commit_group;\n");
}
template <int N>
__device__ __forceinline__ void cpa_wait() {
    asm volatile("cp.async.wait_group %0;\n" :: "n"(N));
}
__device__ __forceinline__ uint32_t f2tf32(float f) {
    uint32_t r;
    asm("cvt.rna.tf32.f32 %0, %1;" : "=r"(r) : "f"(f));
    return r;
}

template <int EPI>
__global__ void __launch_bounds__(256, 2)
tgemm(const float* __restrict__ A, const float* __restrict__ W,
      float* __restrict__ C, int M, int N, int K, int lda,
      const float* __restrict__ ext) {
    extern __shared__ float smem[];
    // layout: A stages at s*STG_U32, B stages at (NSTG+s)*STG_U32
    const int tid  = threadIdx.x;
    const int lane = tid & 31;
    const int wid  = tid >> 5;
    const int wm0 = (wid >> 2) * 64;
    const int wn0 = (wid & 3) * 32;
    const int grp = lane >> 2;         // 0..7
    const int thr = lane & 3;          // 0..3

    const int m0 = blockIdx.y * 128;
    const int n0 = blockIdx.x * 128;

    uint32_t smem_base;
    asm("{ .reg .u64 t; cvta.to.shared.u64 t, %1; cvt.u32.u64 %0, t; }"
        : "=r"(smem_base) : "l"(smem));

    float acc[4][4][4];
    #pragma unroll
    for (int i = 0; i < 4; i++)
        #pragma unroll
        for (int j = 0; j < 4; j++)
            #pragma unroll
            for (int q = 0; q < 4; q++) acc[i][j][q] = 0.f;

    const int row  = tid >> 3;           // 0..31
    const int kq   = (tid & 7) << 2;     // 0,4,..,28

    auto issue = [&](int tile, int stage) {
        int k0 = tile * 32;
        #pragma unroll
        for (int t = 0; t < 4; t++) {
            int r = row + t * 32;
            uint32_t da = smem_base + (stage * STG_U32 + r * SPAD + kq) * 4;
            cpa16(da, A + (size_t)(m0 + r) * lda + k0 + kq, true);
            uint32_t db = smem_base + ((NSTG + stage) * STG_U32 + r * SPAD + kq) * 4;
            cpa16(db, W + (size_t)(n0 + r) * K + k0 + kq, (n0 + r) < N);
        }
        cpa_commit();
    };

    const int T = K >> 5;
    issue(0, 0);
    if (T > 1) issue(1, 1);

    for (int t = 0; t < T; t++) {
        if (t == T - 1) cpa_wait<0>(); else cpa_wait<1>();
        __syncthreads();
        if (t + 2 < T) issue(t + 2, (t + 2) % NSTG);

        const float* As = smem + (t % NSTG) * STG_U32;
        const float* Bs = smem + (NSTG + t % NSTG) * STG_U32;

        #pragma unroll
        for (int ks = 0; ks < 4; ks++) {
            uint32_t af[4][4], bf[4][2];
            #pragma unroll
            for (int ti = 0; ti < 4; ti++) {
                const float* base = &As[(wm0 + ti * 16 + grp) * SPAD + ks * 8 + thr];
                af[ti][0] = f2tf32(base[0]);
                af[ti][1] = f2tf32(base[8 * SPAD]);
                af[ti][2] = f2tf32(base[4]);
                af[ti][3] = f2tf32(base[8 * SPAD + 4]);
            }
            #pragma unroll
            for (int tj = 0; tj < 4; tj++) {
                const float* base = &Bs[(wn0 + tj * 8 + grp) * SPAD + ks * 8 + thr];
                bf[tj][0] = f2tf32(base[0]);
                bf[tj][1] = f2tf32(base[4]);
            }
            #pragma unroll
            for (int ti = 0; ti < 4; ti++)
                #pragma unroll
                for (int tj = 0; tj < 4; tj++) {
                    asm volatile(
                        "mma.sync.aligned.m16n8k8.row.col.f32.tf32.tf32.f32 "
                        "{%0,%1,%2,%3}, {%4,%5,%6,%7}, {%8,%9}, {%0,%1,%2,%3};"
                        : "+f"(acc[ti][tj][0]), "+f"(acc[ti][tj][1]),
                          "+f"(acc[ti][tj][2]), "+f"(acc[ti][tj][3])
                        : "r"(af[ti][0]), "r"(af[ti][1]),
                          "r"(af[ti][2]), "r"(af[ti][3]),
                          "r"(bf[tj][0]), "r"(bf[tj][1]));
                }
        }
    }

    // ---- epilogue (no trailing sync needed; smem not reused after)
    #pragma unroll
    for (int ti = 0; ti < 4; ti++) {
        #pragma unroll
        for (int tj = 0; tj < 4; tj++) {
            int r0 = m0 + wm0 + ti * 16 + grp;
            int c  = n0 + wn0 + tj * 8 + thr * 2;
            if (c < N) {
                #pragma unroll
                for (int half = 0; half < 2; half++) {
                    int r = r0 + half * 8;
                    float v0 = acc[ti][tj][half * 2 + 0];
                    float v1 = acc[ti][tj][half * 2 + 1];
                    if (EPI == 1) {
                        v0 += ext[c];     v1 += ext[c + 1];
                        v0 = (v0 > 20.f) ? v0 : log1pf(__expf(v0));
                        v1 = (v1 > 20.f) ? v1 : log1pf(__expf(v1));
                    } else if (EPI == 2) {
                        v0 += ext[(size_t)r * N + c];
                        v1 += ext[(size_t)r * N + c + 1];
                    }
                    *(float2*)(C + (size_t)r * N + c) = make_float2(v0, v1);
                }
            }
        }
    }
}

// ---------------- Causal depthwise conv (k=4) + bias + SiLU --------------
__global__ void conv_kernel(const float* __restrict__ xz,
                            const float* __restrict__ cw,
                            const float* __restrict__ cb,
                            float* __restrict__ uc) {
    int idx = blockIdx.x * blockDim.x + threadIdx.x;   // over BL*DI/4
    if (idx >= BL * DI / 4) return;
    int dq = idx % (DI / 4);
    int t  = idx / (DI / 4);         // b*L + l
    int d  = dq * 4;
    int l  = t % L_;
    int base = t - l;
    float4 acc = *(const float4*)(cb + d);
    #pragma unroll
    for (int k = 0; k < 4; k++) {
        int ls = l - 3 + k;
        if (ls >= 0) {
            float4 xv = *(const float4*)(xz + (size_t)(base + ls) * (2 * DI) + d);
            acc.x = fmaf(cw[(d + 0) * 4 + k], xv.x, acc.x);
            acc.y = fmaf(cw[(d + 1) * 4 + k], xv.y, acc.y);
            acc.z = fmaf(cw[(d + 2) * 4 + k], xv.z, acc.z);
            acc.w = fmaf(cw[(d + 3) * 4 + k], xv.w, acc.w);
        }
    }
    float4 o;
    o.x = acc.x / (1.f + __expf(-acc.x));
    o.y = acc.y / (1.f + __expf(-acc.y));
    o.z = acc.z / (1.f + __expf(-acc.z));
    o.w = acc.w / (1.f + __expf(-acc.w));
    *(float4*)(uc + (size_t)t * DI + d) = o;
}

// ---------------- Chunked selective scan ---------------------------------
// Block: 256 thr = 16 groups of 16 lanes; 16 consecutive channels d,
// fixed (b, chunk). grid = (DI/16)*B_*NCH.
__global__ void __launch_bounds__(256)
scanA(const float* __restrict__ xd, const float* __restrict__ dl,
      const float* __restrict__ uc, const float* __restrict__ A_log,
      float* __restrict__ hF, float* __restrict__ Pf) {
    int tid = threadIdx.x;
    int grp = tid >> 4, s = tid & 15;
    int blk = blockIdx.x;
    int dgrp = blk & 127;               // DI/16 = 128
    int rest = blk >> 7;
    int chunk = rest & (NCH - 1);
    int b = rest >> 6;
    int d = dgrp * 16 + grp;

    float Av = -__expf(A_log[d * DS + s]);
    float h = 0.f, P = 1.f;
    int l0 = chunk * CL;
    const float* dlp = dl + (size_t)(b * L_ + l0) * DI + d;
    const float* ucp = uc + (size_t)(b * L_ + l0) * DI + d;
    const float* xdp = xd + (size_t)(b * L_ + l0) * XP + DTR + s;

    #pragma unroll 4
    for (int i = 0; i < CL; i++) {
        float delta = dlp[(size_t)i * DI];
        float u     = ucp[(size_t)i * DI];
        float Bt    = xdp[(size_t)i * XP];
        float dA = __expf(delta * Av);
        h = fmaf(dA, h, delta * u * Bt);
        P *= dA;
    }
    size_t o = (((size_t)(b * DI + d)) * NCH + chunk) * DS + s;
    hF[o] = h;
    Pf[o] = P;
}

// Phase B: carry scan across chunks. Thread per (b,d,s).
__global__ void scanB(const float* __restrict__ hF,
                      const float* __restrict__ Pf,
                      float* __restrict__ hI) {
    int idx = blockIdx.x * blockDim.x + threadIdx.x;
    if (idx >= B_ * DI * DS) return;
    size_t base = (size_t)(idx >> 4) * (NCH * DS) + (idx & 15);
    float h = 0.f;
    #pragma unroll 8
    for (int c = 0; c < NCH; c++) {
        size_t o = base + (size_t)c * DS;
        hI[o] = h;
        h = fmaf(Pf[o], h, hF[o]);
    }
}

// Phase C: replay chunk with correct h_in, produce gated y.
__global__ void __launch_bounds__(256)
scanC(const float* __restrict__ xd, const float* __restrict__ dl,
      const float* __restrict__ uc, const float* __restrict__ xz,
      const float* __restrict__ A_log, const float* __restrict__ Dp,
      const float* __restrict__ hI, float* __restrict__ yg) {
    int tid = threadIdx.x;
    int grp = tid >> 4, s = tid & 15;
    int blk = blockIdx.x;
    int dgrp = blk & 127;
    int rest = blk >> 7;
    int chunk = rest & (NCH - 1);
    int b = rest >> 6;
    int d = dgrp * 16 + grp;

    float Av = -__expf(A_log[d * DS + s]);
    float Dd = Dp[d];
    size_t o = (((size_t)(b * DI + d)) * NCH + chunk) * DS + s;
    float h = hI[o];

    int l0 = chunk * CL;
    const float* dlp = dl + (size_t)(b * L_ + l0) * DI + d;
    const float* ucp = uc + (size_t)(b * L_ + l0) * DI + d;
    const float* xdp = xd + (size_t)(b * L_ + l0) * XP + DTR;
    const float* xzp = xz + (size_t)(b * L_ + l0) * (2 * DI) + DI + d;
    float* ygp = yg + (size_t)(b * L_ + l0) * DI + d;

    #pragma unroll 4
    for (int i = 0; i < CL; i++) {
        float delta = dlp[(size_t)i * DI];
        float u     = ucp[(size_t)i * DI];
        float Bt    = xdp[(size_t)i * XP + s];
        float Ct    = xdp[(size_t)i * XP + DS + s];
        float dA = __expf(delta * Av);
        h = fmaf(dA, h, delta * u * Bt);
        float p = h * Ct;
        p += __shfl_xor_sync(0xffffffffu, p, 8, 16);
        p += __shfl_xor_sync(0xffffffffu, p, 4, 16);
        p += __shfl_xor_sync(0xffffffffu, p, 2, 16);
        p += __shfl_xor_sync(0xffffffffu, p, 1, 16);
        if (s == 0) {
            float y = p + u * Dd;
            float r = xzp[(size_t)i * (2 * DI)];
            float sil = r / (1.f + __expf(-r));
            ygp[(size_t)i * DI] = y * sil;
        }
    }
}

// ---------------- launch --------------------------------------------------
#define GSMEM (2 * NSTG * STG_U32 * 4)   // A+B stages, bytes

extern "C" void kernel_launch(void* const* d_in, const int* in_sizes, int n_in,
                              void* d_out, int out_size) {
    const float* x         = (const float*)d_in[0];
    const float* ln_g      = (const float*)d_in[1];
    const float* ln_b      = (const float*)d_in[2];
    const float* in_proj_w = (const float*)d_in[3];   // (2*DI, NE)
    const float* conv_w    = (const float*)d_in[4];   // (DI, 1, 4)
    const float* conv_b    = (const float*)d_in[5];   // (DI)
    const float* x_proj_w  = (const float*)d_in[6];   // (XP, DI)
    const float* dt_proj_w = (const float*)d_in[7];   // (DI, DTR)
    const float* dt_proj_b = (const float*)d_in[8];   // (DI)
    const float* A_log     = (const float*)d_in[9];   // (DI, DS)
    const float* Dp        = (const float*)d_in[10];  // (DI)
    const float* out_w     = (const float*)d_in[11];  // (NE, DI)
    float* out = (float*)d_out;

    float *Xn, *XZ, *Uc, *XD, *Dl, *Yg, *hF, *Pf, *hI;
    cudaGetSymbolAddress((void**)&Xn, g_Xn);
    cudaGetSymbolAddress((void**)&XZ, g_XZ);
    cudaGetSymbolAddress((void**)&Uc, g_Uc);
    cudaGetSymbolAddress((void**)&XD, g_XD);
    cudaGetSymbolAddress((void**)&Dl, g_Dl);
    cudaGetSymbolAddress((void**)&Yg, g_Yg);
    cudaGetSymbolAddress((void**)&hF, g_hF);
    cudaGetSymbolAddress((void**)&Pf, g_Pf);
    cudaGetSymbolAddress((void**)&hI, g_hI);

    static bool attr_set = false;
    if (!attr_set) {
        cudaFuncSetAttribute(tgemm<0>, cudaFuncAttributeMaxDynamicSharedMemorySize, GSMEM);
        cudaFuncSetAttribute(tgemm<1>, cudaFuncAttributeMaxDynamicSharedMemorySize, GSMEM);
        cudaFuncSetAttribute(tgemm<2>, cudaFuncAttributeMaxDynamicSharedMemorySize, GSMEM);
        attr_set = true;
    }

    // 1. LayerNorm
    ln_kernel<<<BL, 256>>>(x, ln_g, ln_b, Xn);

    // 2. in_proj: XZ[4096, 4096] = Xn[4096,1024] @ in_proj_w^T
    tgemm<0><<<dim3(32, 32), 256, GSMEM>>>(Xn, in_proj_w, XZ,
                                           BL, 2 * DI, NE, NE, nullptr);

    // 3. depthwise conv + SiLU on u half -> Uc
    conv_kernel<<<(BL * DI / 4 + 255) / 256, 256>>>(XZ, conv_w, conv_b, Uc);

    // 4. x_proj: XD[4096, 96] = Uc @ x_proj_w^T
    tgemm<0><<<dim3(1, 32), 256, GSMEM>>>(Uc, x_proj_w, XD,
                                          BL, XP, DI, DI, nullptr);

    // 5. dt_proj + softplus
    tgemm<1><<<dim3(16, 32), 256, GSMEM>>>(XD, dt_proj_w, Dl,
                                           BL, DI, DTR, XP, dt_proj_b);

    // 6. chunked selective scan
    scanA<<<(DI / 16) * B_ * NCH, 256>>>(XD, Dl, Uc, A_log, hF, Pf);
    scanB<<<(B_ * DI * DS + 255) / 256, 256>>>(hF, Pf, hI);
    scanC<<<(DI / 16) * B_ * NCH, 256>>>(XD, Dl, Uc, XZ, A_log, Dp, hI, Yg);

    // 7. out_proj + residual: out = Yg @ out_w^T + x
    tgemm<2><<<dim3(8, 32), 256, GSMEM>>>(Yg, out_w, out,
                                          BL, NE, DI, DI, x);
}

// round 6
// speedup vs baseline: 3.4299x; 1.0441x over previous
#include <cuda_runtime.h>
#include <math.h>
#include <stdint.h>

// Problem dims (fixed by the reference)
#define B_    2
#define L_    2048
#define BL    4096          // B_*L_
#define NE    1024          // n_embd
#define DI    2048          // d_inner
#define DS    16            // d_state
#define DTR   64            // dt_rank
#define XP    96            // dt_rank + 2*d_state
#define NCH   128           // scan chunks
#define CL    (L_ / NCH)    // 16 steps per chunk
#define KSPL  8             // split-K factor for x_proj

// ---------------- scratch (static __device__ arrays; no allocation) -------
__device__ float g_Xn[BL * NE];        // layernorm output (tf32-rounded)
__device__ float g_XZ[BL * 2 * DI];    // in_proj output (u | res)
__device__ float g_Uc[BL * DI];        // conv+silu output (exact, for scan)
__device__ float g_UcR[BL * DI];       // conv+silu output (rounded, GEMM in)
__device__ float g_XD[BL * XP];        // x_proj output (cols<64 rounded)
__device__ float g_XDp[KSPL * BL * XP];// x_proj split-K partials
__device__ float g_Dl[BL * DI];        // delta (post softplus, exact)
__device__ float g_Yg[BL * DI];        // scan output, gated (rounded)
__device__ float g_hF[B_ * DI * NCH * DS];
__device__ float g_Pf[B_ * DI * NCH * DS];
__device__ float g_hI[B_ * DI * NCH * DS];
__device__ float g_WinR[2 * DI * NE];  // tf32-rounded weights
__device__ float g_WxR[XP * DI];
__device__ float g_WdtR[DI * DTR];
__device__ float g_WoR[NE * DI];

// ---------------- helpers --------------------------------------------------
__device__ __forceinline__ float rna_tf32(float f) {
    uint32_t r;
    asm("cvt.rna.tf32.f32 %0, %1;" : "=r"(r) : "f"(f));
    return __uint_as_float(r);
}
__device__ __forceinline__ void cpa16(uint32_t dst, const void* src, bool p) {
    int sz = p ? 16 : 0;
    asm volatile("cp.async.cg.shared.global [%0], [%1], 16, %2;\n"
                 :: "r"(dst), "l"(src), "r"(sz));
}
__device__ __forceinline__ void cpa_commit() {
    asm volatile("cp.async.commit_group;\n");
}
template <int N>
__device__ __forceinline__ void cpa_wait() {
    asm volatile("cp.async.wait_group %0;\n" :: "n"(N));
}

// ---------------- weight rounding ------------------------------------------
__global__ void cvt_kernel(const float* __restrict__ src, float* __restrict__ dst,
                           int n4) {
    int i = blockIdx.x * blockDim.x + threadIdx.x;
    if (i >= n4) return;
    float4 v = ((const float4*)src)[i];
    v.x = rna_tf32(v.x); v.y = rna_tf32(v.y);
    v.z = rna_tf32(v.z); v.w = rna_tf32(v.w);
    ((float4*)dst)[i] = v;
}

// ---------------- LayerNorm (output tf32-rounded) --------------------------
__global__ void ln_kernel(const float* __restrict__ x,
                          const float* __restrict__ g,
                          const float* __restrict__ b,
                          float* __restrict__ out) {
    int row = blockIdx.x;
    int tid = threadIdx.x;                    // 0..255, NE/4 == 256
    const float4* xr = (const float4*)(x + (size_t)row * NE);
    float4 v = xr[tid];
    float s  = v.x + v.y + v.z + v.w;
    float s2 = v.x*v.x + v.y*v.y + v.z*v.z + v.w*v.w;

    __shared__ float red0[8], red1[8];
    __shared__ float mv[2];
    int wid = tid >> 5, lane = tid & 31;
    #pragma unroll
    for (int o = 16; o; o >>= 1) {
        s  += __shfl_xor_sync(0xffffffffu, s,  o);
        s2 += __shfl_xor_sync(0xffffffffu, s2, o);
    }
    if (lane == 0) { red0[wid] = s; red1[wid] = s2; }
    __syncthreads();
    if (tid == 0) {
        float a = 0.f, c = 0.f;
        #pragma unroll
        for (int i = 0; i < 8; i++) { a += red0[i]; c += red1[i]; }
        float mean = a * (1.0f / NE);
        float var  = c * (1.0f / NE) - mean * mean;
        mv[0] = mean;
        mv[1] = rsqrtf(var + 1e-5f);
    }
    __syncthreads();
    float mean = mv[0], inv = mv[1];
    float4 gv = ((const float4*)g)[tid];
    float4 bv = ((const float4*)b)[tid];
    float4 o4;
    o4.x = rna_tf32((v.x - mean) * inv * gv.x + bv.x);
    o4.y = rna_tf32((v.y - mean) * inv * gv.y + bv.y);
    o4.z = rna_tf32((v.z - mean) * inv * gv.z + bv.z);
    o4.w = rna_tf32((v.w - mean) * inv * gv.w + bv.w);
    ((float4*)(out + (size_t)row * NE))[tid] = o4;
}

// ---------------- TF32 mma.sync GEMM, 3-stage cp.async ---------------------
// C[M,N] = A[M,K] @ W[N,K]^T, inputs pre-rounded to tf32 (no cvt in loop).
// BM=BN=128, BK=32, 256 thr, warps 2(m)x4(n), 64x32 per warp via m16n8k8.
// Split-K via blockIdx.z: A,W advance z*K in k; C advances z*zoffC.
// EPI: 0 none, 1 softplus(acc+ext[n]), 2 acc+ext[m*N+n]
#define SPAD 36                    // smem row stride floats (conflict-free)
#define STG_U32 (128 * SPAD)       // u32 per tile buffer
#define NSTG 3
#define GSMEM (2 * NSTG * STG_U32 * 4)

template <int EPI>
__global__ void __launch_bounds__(256, 2)
tgemm(const float* __restrict__ A, const float* __restrict__ W,
      float* __restrict__ C, int M, int N, int K, int lda, int ldw,
      const float* __restrict__ ext, size_t zoffC) {
    extern __shared__ float smem[];
    const int tid  = threadIdx.x;
    const int lane = tid & 31;
    const int wid  = tid >> 5;
    const int wm0 = (wid >> 2) * 64;
    const int wn0 = (wid & 3) * 32;
    const int grp = lane >> 2;         // 0..7
    const int thr = lane & 3;          // 0..3

    const int m0 = blockIdx.y * 128;
    const int n0 = blockIdx.x * 128;
    const int kz = blockIdx.z * K;     // split-K base
    C += (size_t)blockIdx.z * zoffC;

    uint32_t smem_base;
    asm("{ .reg .u64 t; cvta.to.shared.u64 t, %1; cvt.u32.u64 %0, t; }"
        : "=r"(smem_base) : "l"(smem));

    float acc[4][4][4];
    #pragma unroll
    for (int i = 0; i < 4; i++)
        #pragma unroll
        for (int j = 0; j < 4; j++)
            #pragma unroll
            for (int q = 0; q < 4; q++) acc[i][j][q] = 0.f;

    const int row  = tid >> 3;           // 0..31
    const int kq   = (tid & 7) << 2;     // 0,4,..,28

    auto issue = [&](int tile, int stage) {
        int k0 = kz + tile * 32;
        #pragma unroll
        for (int t = 0; t < 4; t++) {
            int r = row + t * 32;
            uint32_t da = smem_base + (stage * STG_U32 + r * SPAD + kq) * 4;
            cpa16(da, A + (size_t)(m0 + r) * lda + k0 + kq, true);
            uint32_t db = smem_base + ((NSTG + stage) * STG_U32 + r * SPAD + kq) * 4;
            cpa16(db, W + (size_t)(n0 + r) * ldw + k0 + kq, (n0 + r) < N);
        }
        cpa_commit();
    };

    const int T = K >> 5;
    issue(0, 0);
    if (T > 1) issue(1, 1);

    for (int t = 0; t < T; t++) {
        if (t == T - 1) cpa_wait<0>(); else cpa_wait<1>();
        __syncthreads();
        if (t + 2 < T) issue(t + 2, (t + 2) % NSTG);

        const uint32_t* As = (const uint32_t*)smem + (t % NSTG) * STG_U32;
        const uint32_t* Bs = (const uint32_t*)smem + (NSTG + t % NSTG) * STG_U32;

        #pragma unroll
        for (int ks = 0; ks < 4; ks++) {
            uint32_t af[4][4], bf[4][2];
            #pragma unroll
            for (int ti = 0; ti < 4; ti++) {
                const uint32_t* base = &As[(wm0 + ti * 16 + grp) * SPAD + ks * 8 + thr];
                af[ti][0] = base[0];
                af[ti][1] = base[8 * SPAD];
                af[ti][2] = base[4];
                af[ti][3] = base[8 * SPAD + 4];
            }
            #pragma unroll
            for (int tj = 0; tj < 4; tj++) {
                const uint32_t* base = &Bs[(wn0 + tj * 8 + grp) * SPAD + ks * 8 + thr];
                bf[tj][0] = base[0];
                bf[tj][1] = base[4];
            }
            #pragma unroll
            for (int ti = 0; ti < 4; ti++)
                #pragma unroll
                for (int tj = 0; tj < 4; tj++) {
                    asm volatile(
                        "mma.sync.aligned.m16n8k8.row.col.f32.tf32.tf32.f32 "
                        "{%0,%1,%2,%3}, {%4,%5,%6,%7}, {%8,%9}, {%0,%1,%2,%3};"
                        : "+f"(acc[ti][tj][0]), "+f"(acc[ti][tj][1]),
                          "+f"(acc[ti][tj][2]), "+f"(acc[ti][tj][3])
                        : "r"(af[ti][0]), "r"(af[ti][1]),
                          "r"(af[ti][2]), "r"(af[ti][3]),
                          "r"(bf[tj][0]), "r"(bf[tj][1]));
                }
        }
    }

    // ---- epilogue
    #pragma unroll
    for (int ti = 0; ti < 4; ti++) {
        #pragma unroll
        for (int tj = 0; tj < 4; tj++) {
            int r0 = m0 + wm0 + ti * 16 + grp;
            int c  = n0 + wn0 + tj * 8 + thr * 2;
            if (c < N) {
                #pragma unroll
                for (int half = 0; half < 2; half++) {
                    int r = r0 + half * 8;
                    float v0 = acc[ti][tj][half * 2 + 0];
                    float v1 = acc[ti][tj][half * 2 + 1];
                    if (EPI == 1) {
                        v0 += ext[c];     v1 += ext[c + 1];
                        v0 = (v0 > 20.f) ? v0 : log1pf(__expf(v0));
                        v1 = (v1 > 20.f) ? v1 : log1pf(__expf(v1));
                    } else if (EPI == 2) {
                        v0 += ext[(size_t)r * N + c];
                        v1 += ext[(size_t)r * N + c + 1];
                    }
                    *(float2*)(C + (size_t)r * N + c) = make_float2(v0, v1);
                }
            }
        }
    }
}

// ---------------- x_proj split-K reduction (+ rna on dt cols) --------------
__global__ void xred_kernel(const float* __restrict__ p, float* __restrict__ out) {
    int i = blockIdx.x * blockDim.x + threadIdx.x;   // over BL*XP/4
    if (i >= BL * XP / 4) return;
    float4 a = ((const float4*)p)[i];
    #pragma unroll
    for (int s = 1; s < KSPL; s++) {
        float4 v = ((const float4*)(p + (size_t)s * BL * XP))[i];
        a.x += v.x; a.y += v.y; a.z += v.z; a.w += v.w;
    }
    int colg = i % (XP / 4);           // float4 group within row
    if (colg < DTR / 4) {              // dt-rank columns: pre-round for GEMM
        a.x = rna_tf32(a.x); a.y = rna_tf32(a.y);
        a.z = rna_tf32(a.z); a.w = rna_tf32(a.w);
    }
    ((float4*)out)[i] = a;
}

// ---------------- Causal depthwise conv (k=4) + bias + SiLU ---------------
__global__ void conv_kernel(const float* __restrict__ xz,
                            const float* __restrict__ cw,
                            const float* __restrict__ cb,
                            float* __restrict__ uc,
                            float* __restrict__ ucr) {
    int idx = blockIdx.x * blockDim.x + threadIdx.x;   // over BL*DI/4
    if (idx >= BL * DI / 4) return;
    int dq = idx % (DI / 4);
    int t  = idx / (DI / 4);         // b*L + l
    int d  = dq * 4;
    int l  = t % L_;
    int base = t - l;
    float4 acc = *(const float4*)(cb + d);
    #pragma unroll
    for (int k = 0; k < 4; k++) {
        int ls = l - 3 + k;
        if (ls >= 0) {
            float4 xv = *(const float4*)(xz + (size_t)(base + ls) * (2 * DI) + d);
            acc.x = fmaf(cw[(d + 0) * 4 + k], xv.x, acc.x);
            acc.y = fmaf(cw[(d + 1) * 4 + k], xv.y, acc.y);
            acc.z = fmaf(cw[(d + 2) * 4 + k], xv.z, acc.z);
            acc.w = fmaf(cw[(d + 3) * 4 + k], xv.w, acc.w);
        }
    }
    float4 o;
    o.x = acc.x / (1.f + __expf(-acc.x));
    o.y = acc.y / (1.f + __expf(-acc.y));
    o.z = acc.z / (1.f + __expf(-acc.z));
    o.w = acc.w / (1.f + __expf(-acc.w));
    *(float4*)(uc + (size_t)t * DI + d) = o;
    float4 orr;
    orr.x = rna_tf32(o.x); orr.y = rna_tf32(o.y);
    orr.z = rna_tf32(o.z); orr.w = rna_tf32(o.w);
    *(float4*)(ucr + (size_t)t * DI + d) = orr;
}

// ---------------- Chunked selective scan -----------------------------------
// Block: 256 thr = 16 groups of 16 lanes; 16 consecutive channels d,
// fixed (b, chunk). grid = (DI/16)*NCH*B_.
__global__ void __launch_bounds__(256)
scanA(const float* __restrict__ xd, const float* __restrict__ dl,
      const float* __restrict__ uc, const float* __restrict__ A_log,
      float* __restrict__ hF, float* __restrict__ Pf) {
    int tid = threadIdx.x;
    int grp = tid >> 4, s = tid & 15;
    int blk = blockIdx.x;
    int dgrp = blk & 127;               // DI/16 = 128
    int rest = blk >> 7;
    int chunk = rest & (NCH - 1);
    int b = rest >> 7;
    int d = dgrp * 16 + grp;

    float Av = -__expf(A_log[d * DS + s]);
    float h = 0.f, P = 1.f;
    int l0 = chunk * CL;
    const float* dlp = dl + (size_t)(b * L_ + l0) * DI + d;
    const float* ucp = uc + (size_t)(b * L_ + l0) * DI + d;
    const float* xdp = xd + (size_t)(b * L_ + l0) * XP + DTR + s;

    #pragma unroll 4
    for (int i = 0; i < CL; i++) {
        float delta = dlp[(size_t)i * DI];
        float u     = ucp[(size_t)i * DI];
        float Bt    = xdp[(size_t)i * XP];
        float dA = __expf(delta * Av);
        h = fmaf(dA, h, delta * u * Bt);
        P *= dA;
    }
    size_t o = (((size_t)(b * DI + d)) * NCH + chunk) * DS + s;
    hF[o] = h;
    Pf[o] = P;
}

// Phase B: carry scan across chunks. Thread per (b,d,s).
__global__ void scanB(const float* __restrict__ hF,
                      const float* __restrict__ Pf,
                      float* __restrict__ hI) {
    int idx = blockIdx.x * blockDim.x + threadIdx.x;
    if (idx >= B_ * DI * DS) return;
    size_t base = (size_t)(idx >> 4) * (NCH * DS) + (idx & 15);
    float h = 0.f;
    #pragma unroll 8
    for (int c = 0; c < NCH; c++) {
        size_t o = base + (size_t)c * DS;
        hI[o] = h;
        h = fmaf(Pf[o], h, hF[o]);
    }
}

// Phase C: replay chunk with correct h_in, produce gated y (tf32-rounded).
__global__ void __launch_bounds__(256)
scanC(const float* __restrict__ xd, const float* __restrict__ dl,
      const float* __restrict__ uc, const float* __restrict__ xz,
      const float* __restrict__ A_log, const float* __restrict__ Dp,
      const float* __restrict__ hI, float* __restrict__ yg) {
    int tid = threadIdx.x;
    int grp = tid >> 4, s = tid & 15;
    int blk = blockIdx.x;
    int dgrp = blk & 127;
    int rest = blk >> 7;
    int chunk = rest & (NCH - 1);
    int b = rest >> 7;
    int d = dgrp * 16 + grp;

    float Av = -__expf(A_log[d * DS + s]);
    float Dd = Dp[d];
    size_t o = (((size_t)(b * DI + d)) * NCH + chunk) * DS + s;
    float h = hI[o];

    int l0 = chunk * CL;
    const float* dlp = dl + (size_t)(b * L_ + l0) * DI + d;
    const float* ucp = uc + (size_t)(b * L_ + l0) * DI + d;
    const float* xdp = xd + (size_t)(b * L_ + l0) * XP + DTR;
    const float* xzp = xz + (size_t)(b * L_ + l0) * (2 * DI) + DI + d;
    float* ygp = yg + (size_t)(b * L_ + l0) * DI + d;

    #pragma unroll 4
    for (int i = 0; i < CL; i++) {
        float delta = dlp[(size_t)i * DI];
        float u     = ucp[(size_t)i * DI];
        float Bt    = xdp[(size_t)i * XP + s];
        float Ct    = xdp[(size_t)i * XP + DS + s];
        float dA = __expf(delta * Av);
        h = fmaf(dA, h, delta * u * Bt);
        float p = h * Ct;
        p += __shfl_xor_sync(0xffffffffu, p, 8, 16);
        p += __shfl_xor_sync(0xffffffffu, p, 4, 16);
        p += __shfl_xor_sync(0xffffffffu, p, 2, 16);
        p += __shfl_xor_sync(0xffffffffu, p, 1, 16);
        if (s == 0) {
            float y = p + u * Dd;
            float rz = xzp[(size_t)i * (2 * DI)];
            float sil = rz / (1.f + __expf(-rz));
            ygp[(size_t)i * DI] = rna_tf32(y * sil);
        }
    }
}

// ---------------- launch ----------------------------------------------------
extern "C" void kernel_launch(void* const* d_in, const int* in_sizes, int n_in,
                              void* d_out, int out_size) {
    const float* x         = (const float*)d_in[0];
    const float* ln_g      = (const float*)d_in[1];
    const float* ln_b      = (const float*)d_in[2];
    const float* in_proj_w = (const float*)d_in[3];   // (2*DI, NE)
    const float* conv_w    = (const float*)d_in[4];   // (DI, 1, 4)
    const float* conv_b    = (const float*)d_in[5];   // (DI)
    const float* x_proj_w  = (const float*)d_in[6];   // (XP, DI)
    const float* dt_proj_w = (const float*)d_in[7];   // (DI, DTR)
    const float* dt_proj_b = (const float*)d_in[8];   // (DI)
    const float* A_log     = (const float*)d_in[9];   // (DI, DS)
    const float* Dp        = (const float*)d_in[10];  // (DI)
    const float* out_w     = (const float*)d_in[11];  // (NE, DI)
    float* out = (float*)d_out;

    float *Xn, *XZ, *Uc, *UcR, *XD, *XDp, *Dl, *Yg, *hF, *Pf, *hI;
    float *WinR, *WxR, *WdtR, *WoR;
    cudaGetSymbolAddress((void**)&Xn, g_Xn);
    cudaGetSymbolAddress((void**)&XZ, g_XZ);
    cudaGetSymbolAddress((void**)&Uc, g_Uc);
    cudaGetSymbolAddress((void**)&UcR, g_UcR);
    cudaGetSymbolAddress((void**)&XD, g_XD);
    cudaGetSymbolAddress((void**)&XDp, g_XDp);
    cudaGetSymbolAddress((void**)&Dl, g_Dl);
    cudaGetSymbolAddress((void**)&Yg, g_Yg);
    cudaGetSymbolAddress((void**)&hF, g_hF);
    cudaGetSymbolAddress((void**)&Pf, g_Pf);
    cudaGetSymbolAddress((void**)&hI, g_hI);
    cudaGetSymbolAddress((void**)&WinR, g_WinR);
    cudaGetSymbolAddress((void**)&WxR, g_WxR);
    cudaGetSymbolAddress((void**)&WdtR, g_WdtR);
    cudaGetSymbolAddress((void**)&WoR, g_WoR);

    cudaFuncSetAttribute(tgemm<0>, cudaFuncAttributeMaxDynamicSharedMemorySize, GSMEM);
    cudaFuncSetAttribute(tgemm<1>, cudaFuncAttributeMaxDynamicSharedMemorySize, GSMEM);
    cudaFuncSetAttribute(tgemm<2>, cudaFuncAttributeMaxDynamicSharedMemorySize, GSMEM);

    // 0. round weights to tf32 (rna)
    cvt_kernel<<<(2*DI*NE/4 + 255)/256, 256>>>(in_proj_w, WinR, 2*DI*NE/4);
    cvt_kernel<<<(XP*DI/4  + 255)/256, 256>>>(x_proj_w,  WxR,  XP*DI/4);
    cvt_kernel<<<(DI*DTR/4 + 255)/256, 256>>>(dt_proj_w, WdtR, DI*DTR/4);
    cvt_kernel<<<(NE*DI/4  + 255)/256, 256>>>(out_w,     WoR,  NE*DI/4);

    // 1. LayerNorm (rounded output)
    ln_kernel<<<BL, 256>>>(x, ln_g, ln_b, Xn);

    // 2. in_proj: XZ[4096,4096] = Xn @ WinR^T
    tgemm<0><<<dim3(32, 32, 1), 256, GSMEM>>>(Xn, WinR, XZ,
                                              BL, 2 * DI, NE, NE, NE, nullptr, 0);

    // 3. depthwise conv + SiLU -> Uc (exact) + UcR (rounded)
    conv_kernel<<<(BL * DI / 4 + 255) / 256, 256>>>(XZ, conv_w, conv_b, Uc, UcR);

    // 4. x_proj via split-K: XDp[z] = UcR[:, z*256:(z+1)*256] @ WxR^T-slice
    tgemm<0><<<dim3(1, 32, KSPL), 256, GSMEM>>>(UcR, WxR, XDp,
                                                BL, XP, DI / KSPL, DI, DI,
                                                nullptr, (size_t)BL * XP);
    xred_kernel<<<(BL * XP / 4 + 255) / 256, 256>>>(XDp, XD);

    // 5. dt_proj + softplus: Dl = softplus(XD[:, :64] @ WdtR^T + b)
    tgemm<1><<<dim3(16, 32, 1), 256, GSMEM>>>(XD, WdtR, Dl,
                                              BL, DI, DTR, XP, DTR, dt_proj_b, 0);

    // 6. chunked selective scan
    scanA<<<(DI / 16) * B_ * NCH, 256>>>(XD, Dl, Uc, A_log, hF, Pf);
    scanB<<<(B_ * DI * DS + 255) / 256, 256>>>(hF, Pf, hI);
    scanC<<<(DI / 16) * B_ * NCH, 256>>>(XD, Dl, Uc, XZ, A_log, Dp, hI, Yg);

    // 7. out_proj + residual: out = Yg @ WoR^T + x
    tgemm<2><<<dim3(8, 32, 1), 256, GSMEM>>>(Yg, WoR, out,
                                             BL, NE, DI, DI, DI, x, 0);
}